// round 4
// baseline (speedup 1.0000x reference)
#include <cuda_runtime.h>
#include <math.h>

#define T_MAX 16384
#define N1D 16
#define N2D 16
#define N3D 8
#define SDIM 2048
#define MDIM 16

// ---- device scratch (no allocations allowed) ----
__device__ float g_em[T_MAX * SDIM];       // exp(em[t,s] - rowmax[t])  (128 MB)
__device__ float g_mx[T_MAX];              // rowmax[t]
__device__ float g_loglamT[MDIM * SDIM];   // log(lam_c) transposed: [m][s]
__device__ float g_lamsum[SDIM];
__device__ float g_pi[SDIM];               // exp(combined logpi)

// ---- f32x2 packed-FMA helpers (sm_100+/sm_103a) ----
__device__ __forceinline__ unsigned long long pk2(float lo, float hi) {
    unsigned long long r;
    asm("mov.b64 %0, {%1, %2};" : "=l"(r) : "f"(lo), "f"(hi));
    return r;
}
__device__ __forceinline__ void upk2(unsigned long long v, float& lo, float& hi) {
    asm("mov.b64 {%0, %1}, %2;" : "=f"(lo), "=f"(hi) : "l"(v));
}
__device__ __forceinline__ unsigned long long fma2(unsigned long long a,
                                                   unsigned long long b,
                                                   unsigned long long c) {
    unsigned long long d;
    asm("fma.rn.f32x2 %0, %1, %2, %3;" : "=l"(d) : "l"(a), "l"(b), "l"(c));
    return d;
}
__device__ __forceinline__ unsigned long long mul2(unsigned long long a,
                                                   unsigned long long b) {
    unsigned long long d;
    asm("mul.rn.f32x2 %0, %1, %2;" : "=l"(d) : "l"(a), "l"(b));
    return d;
}
__device__ __forceinline__ float hadd2(unsigned long long v) {
    float lo, hi;
    upk2(v, lo, hi);
    return lo + hi;
}

// ============================================================
// Kernel 1: combined rates, log-rates (transposed), priors
// ============================================================
__global__ void setup_kernel(const float* __restrict__ lam1,
                             const float* __restrict__ lam2,
                             const float* __restrict__ lam3,
                             const float* __restrict__ logpi1,
                             const float* __restrict__ logpi2,
                             const float* __restrict__ logpi3) {
    int s = blockIdx.x * blockDim.x + threadIdx.x;
    if (s >= SDIM) return;
    int s1 = s >> 7, s2 = (s >> 3) & 15, s3 = s & 7;
    float lsum = 0.f;
#pragma unroll
    for (int m = 0; m < MDIM; m++) {
        float lam = lam1[s1 * MDIM + m] + lam2[s2 * MDIM + m] + lam3[s3 * MDIM + m];
        lsum += lam;
        g_loglamT[m * SDIM + s] = logf(lam);
    }
    g_lamsum[s] = lsum;
    g_pi[s] = expf(logpi1[s1] + logpi2[s2] + logpi3[s3]);
}

// ============================================================
// Kernel 2: per-timestep emissions, normalized to exp(em - max)
// ============================================================
__global__ void emis_kernel(const int* __restrict__ x) {
    int t = blockIdx.x;
    int tid = threadIdx.x;
    __shared__ float xf[MDIM];
    __shared__ float red[8];

    if (tid < MDIM) xf[tid] = (float)x[t * MDIM + tid];
    __syncthreads();

    float lg = 0.f;
#pragma unroll
    for (int m = 0; m < MDIM; m++) lg += lgammaf(xf[m] + 1.0f);

    float e[8];
#pragma unroll
    for (int j = 0; j < 8; j++) e[j] = 0.f;

#pragma unroll
    for (int m = 0; m < MDIM; m++) {
        float xm = xf[m];
        const float* row = &g_loglamT[m * SDIM];
#pragma unroll
        for (int j = 0; j < 8; j++) e[j] = fmaf(xm, row[tid + j * 256], e[j]);
    }
#pragma unroll
    for (int j = 0; j < 8; j++) e[j] = e[j] - g_lamsum[tid + j * 256] - lg;

    float mloc = -3.4e38f;
#pragma unroll
    for (int j = 0; j < 8; j++) mloc = fmaxf(mloc, e[j]);
#pragma unroll
    for (int o = 16; o > 0; o >>= 1)
        mloc = fmaxf(mloc, __shfl_xor_sync(0xffffffffu, mloc, o));
    if ((tid & 31) == 0) red[tid >> 5] = mloc;
    __syncthreads();
    float mx = red[0];
#pragma unroll
    for (int k = 1; k < 8; k++) mx = fmaxf(mx, red[k]);

    float* outrow = &g_em[t * SDIM];
#pragma unroll
    for (int j = 0; j < 8; j++) outrow[tid + j * 256] = expf(e[j] - mx);
    if (tid == 0) g_mx[t] = mx;
}

// ============================================================
// Kernel 3: persistent single-CTA scaled-linear forward scan.
// a[d1][d2][d3], d1-stride 132 floats (pad kills 8-way STS conflict;
// 132*4 = 528 B = 16B-multiple so float4/ulonglong2 loads stay aligned).
// b[p1][d3][p2] (row stride 16), c[p1][d2][d3].
// ============================================================
__global__ void __launch_bounds__(1024, 1)
scan_kernel(const float* __restrict__ logA1,
            const float* __restrict__ logA2,
            const float* __restrict__ logA3,
            float* __restrict__ out) {
    __shared__ __align__(16) float Abuf1[N1D * N1D];   // exp(logA1)
    __shared__ __align__(16) float Abuf2[N2D * N2D];   // exp(logA2)
    __shared__ __align__(16) float aS[2][N1D * 132];
    __shared__ __align__(16) float bS[N1D * N3D * 16];
    __shared__ __align__(16) float cS[N1D * N2D * N3D];
    __shared__ float wsum[32];
    __shared__ float SfinInv[1];

    const int tid = threadIdx.x;
    const int warp = tid >> 5, lane = tid & 31;

    if (tid < 256) Abuf1[tid] = expf(logA1[tid]);
    else if (tid < 512) Abuf2[tid - 256] = expf(logA2[tid - 256]);

    // ---- phase-2 role: pair=(p1,p2), sub -> d3 in {sub, sub+4}
    const int p2_pair = tid >> 2;
    const int p2_p1 = p2_pair >> 4, p2_p2 = p2_pair & 15;
    const int p2_sub = tid & 3;
    // packed A3 row pairs: A3p0[j] = (A3[sub][2j], A3[sub][2j+1])
    unsigned long long A3p0[4], A3p1[4];
#pragma unroll
    for (int j = 0; j < 4; j++) {
        A3p0[j] = pk2(expf(logA3[p2_sub * 8 + 2 * j]),
                      expf(logA3[p2_sub * 8 + 2 * j + 1]));
        A3p1[j] = pk2(expf(logA3[(p2_sub + 4) * 8 + 2 * j]),
                      expf(logA3[(p2_sub + 4) * 8 + 2 * j + 1]));
    }
    // ---- phase-3 role: grp=(p1,d3), sub -> d2 in {sub, sub+8}
    const int p3_grp = tid >> 3;
    const int p3_p1 = p3_grp >> 3, p3_d3 = p3_grp & 7;
    const int p3_sub = tid & 7;
    // ---- phase-4 role: grp=(d2,d3), sub -> d1 in {sub, sub+8}
    const int p4_grp = tid >> 3;
    const int p4_d2 = p4_grp >> 3, p4_d3 = p4_grp & 7;
    const int p4_sub = tid & 7;
    const int em_i0 = p4_sub * 128 + p4_d2 * 8 + p4_d3;
    const int em_i1 = (p4_sub + 8) * 128 + p4_d2 * 8 + p4_d3;
    const int aw_i0 = p4_sub * 132 + p4_d2 * 8 + p4_d3;
    const int aw_i1 = (p4_sub + 8) * 132 + p4_d2 * 8 + p4_d3;

    double Lacc = 0.0;
    float mx_reg = g_mx[0];

    __syncthreads();

    // ---- t = 0: u = em0 * pi
    {
        float u0 = g_em[em_i0] * g_pi[em_i0];
        float u1 = g_em[em_i1] * g_pi[em_i1];
        aS[0][aw_i0] = u0;
        aS[0][aw_i1] = u1;
        float ps = u0 + u1;
#pragma unroll
        for (int o = 16; o > 0; o >>= 1) ps += __shfl_xor_sync(0xffffffffu, ps, o);
        if (lane == 0) wsum[warp] = ps;
    }
    __syncthreads();

    for (int t = 1; t < T_MAX; t++) {
        const float* acur = aS[(t - 1) & 1];
        float* anext = aS[t & 1];

        if (warp == 0) {
            float s = wsum[lane];
#pragma unroll
            for (int o = 16; o > 0; o >>= 1) s += __shfl_xor_sync(0xffffffffu, s, o);
            if (lane == 0) {
                SfinInv[0] = 1.0f / s;
                Lacc += (double)(mx_reg + logf(s));
            }
        }
        if (tid == 0) mx_reg = g_mx[t];

        float eg0 = g_em[t * SDIM + em_i0];
        float eg1 = g_em[t * SDIM + em_i1];

        // ---- phase 2: b[p1,d3,p2] = sum_p3 A3[d3,p3] * a[p1,p2,p3]
        {
            const ulonglong2* ap = (const ulonglong2*)(acur + p2_p1 * 132 + p2_p2 * 8);
            ulonglong2 V0 = ap[0];     // (a0,a1),(a2,a3)
            ulonglong2 V1 = ap[1];     // (a4,a5),(a6,a7)
            unsigned long long acc0 = mul2(A3p0[0], V0.x);
            acc0 = fma2(A3p0[1], V0.y, acc0);
            acc0 = fma2(A3p0[2], V1.x, acc0);
            acc0 = fma2(A3p0[3], V1.y, acc0);
            unsigned long long acc1 = mul2(A3p1[0], V0.x);
            acc1 = fma2(A3p1[1], V0.y, acc1);
            acc1 = fma2(A3p1[2], V1.x, acc1);
            acc1 = fma2(A3p1[3], V1.y, acc1);
            bS[(p2_p1 * 8 + p2_sub) * 16 + p2_p2] = hadd2(acc0);
            bS[(p2_p1 * 8 + p2_sub + 4) * 16 + p2_p2] = hadd2(acc1);
        }
        __syncthreads();

        // ---- phase 3: c[p1,d2,d3] = sum_p2 A2[d2,p2] * b[p1,d3,p2]
        {
            const ulonglong2* bp = (const ulonglong2*)(bS + (p3_p1 * 8 + p3_d3) * 16);
            ulonglong2 B0 = bp[0], B1 = bp[1], B2 = bp[2], B3 = bp[3];
            const ulonglong2* w0 = (const ulonglong2*)(Abuf2 + p3_sub * 16);
            const ulonglong2* w1 = (const ulonglong2*)(Abuf2 + (p3_sub + 8) * 16);
            ulonglong2 W0a = w0[0], W0b = w0[1], W0c = w0[2], W0d = w0[3];
            unsigned long long acc0 = mul2(W0a.x, B0.x);
            acc0 = fma2(W0a.y, B0.y, acc0);
            acc0 = fma2(W0b.x, B1.x, acc0);
            acc0 = fma2(W0b.y, B1.y, acc0);
            acc0 = fma2(W0c.x, B2.x, acc0);
            acc0 = fma2(W0c.y, B2.y, acc0);
            acc0 = fma2(W0d.x, B3.x, acc0);
            acc0 = fma2(W0d.y, B3.y, acc0);
            ulonglong2 W1a = w1[0], W1b = w1[1], W1c = w1[2], W1d = w1[3];
            unsigned long long acc1 = mul2(W1a.x, B0.x);
            acc1 = fma2(W1a.y, B0.y, acc1);
            acc1 = fma2(W1b.x, B1.x, acc1);
            acc1 = fma2(W1b.y, B1.y, acc1);
            acc1 = fma2(W1c.x, B2.x, acc1);
            acc1 = fma2(W1c.y, B2.y, acc1);
            acc1 = fma2(W1d.x, B3.x, acc1);
            acc1 = fma2(W1d.y, B3.y, acc1);
            cS[(p3_p1 * 16 + p3_sub) * 8 + p3_d3] = hadd2(acc0);
            cS[(p3_p1 * 16 + p3_sub + 8) * 8 + p3_d3] = hadd2(acc1);
        }
        __syncthreads();

        // ---- phase 4: u[d] = em * invS * sum_p1 A1[d1,p1] * c[p1,d2,d3]
        {
            // strided gather (8-way broadcast within each lane-group, conflict-free)
            unsigned long long cvp[8];
#pragma unroll
            for (int j = 0; j < 8; j++) {
                float c0 = cS[((2 * j) * 16 + p4_d2) * 8 + p4_d3];
                float c1 = cS[((2 * j + 1) * 16 + p4_d2) * 8 + p4_d3];
                cvp[j] = pk2(c0, c1);   // ALU-pipe pack, FMA pipe stays free
            }
            const ulonglong2* w0 = (const ulonglong2*)(Abuf1 + p4_sub * 16);
            const ulonglong2* w1 = (const ulonglong2*)(Abuf1 + (p4_sub + 8) * 16);
            ulonglong2 W0a = w0[0], W0b = w0[1], W0c = w0[2], W0d = w0[3];
            unsigned long long acc0 = mul2(W0a.x, cvp[0]);
            acc0 = fma2(W0a.y, cvp[1], acc0);
            acc0 = fma2(W0b.x, cvp[2], acc0);
            acc0 = fma2(W0b.y, cvp[3], acc0);
            acc0 = fma2(W0c.x, cvp[4], acc0);
            acc0 = fma2(W0c.y, cvp[5], acc0);
            acc0 = fma2(W0d.x, cvp[6], acc0);
            acc0 = fma2(W0d.y, cvp[7], acc0);
            ulonglong2 W1a = w1[0], W1b = w1[1], W1c = w1[2], W1d = w1[3];
            unsigned long long acc1 = mul2(W1a.x, cvp[0]);
            acc1 = fma2(W1a.y, cvp[1], acc1);
            acc1 = fma2(W1b.x, cvp[2], acc1);
            acc1 = fma2(W1c.x, cvp[4], acc1);
            acc1 = fma2(W1b.y, cvp[3], acc1);
            acc1 = fma2(W1c.y, cvp[5], acc1);
            acc1 = fma2(W1d.x, cvp[6], acc1);
            acc1 = fma2(W1d.y, cvp[7], acc1);
            float invS = SfinInv[0];
            float u0 = eg0 * invS * hadd2(acc0);
            float u1 = eg1 * invS * hadd2(acc1);
            anext[aw_i0] = u0;
            anext[aw_i1] = u1;
            float ps = u0 + u1;
#pragma unroll
            for (int o = 16; o > 0; o >>= 1) ps += __shfl_xor_sync(0xffffffffu, ps, o);
            if (lane == 0) wsum[warp] = ps;
        }
        __syncthreads();
    }

    if (warp == 0) {
        float s = wsum[lane];
#pragma unroll
        for (int o = 16; o > 0; o >>= 1) s += __shfl_xor_sync(0xffffffffu, s, o);
        if (lane == 0) {
            Lacc += (double)(mx_reg + logf(s));
            out[0] = (float)Lacc;
        }
    }
}

// ============================================================
extern "C" void kernel_launch(void* const* d_in, const int* in_sizes, int n_in,
                              void* d_out, int out_size) {
    const int*   x      = (const int*)d_in[0];
    const float* lam1   = (const float*)d_in[1];
    const float* lam2   = (const float*)d_in[2];
    const float* lam3   = (const float*)d_in[3];
    const float* logA1  = (const float*)d_in[4];
    const float* logA2  = (const float*)d_in[5];
    const float* logA3  = (const float*)d_in[6];
    const float* logpi1 = (const float*)d_in[7];
    const float* logpi2 = (const float*)d_in[8];
    const float* logpi3 = (const float*)d_in[9];
    float* out = (float*)d_out;

    setup_kernel<<<8, 256>>>(lam1, lam2, lam3, logpi1, logpi2, logpi3);
    emis_kernel<<<T_MAX, 256>>>(x);
    scan_kernel<<<1, 1024>>>(logA1, logA2, logA3, out);
}

// round 5
// speedup vs baseline: 2.7410x; 2.7410x over previous
#include <cuda_runtime.h>
#include <math.h>

#define T_MAX 16384
#define SDIM 2048
#define MDIM 16

// ---- device scratch (no allocations allowed) ----
__device__ float g_em[T_MAX * SDIM];       // exp(em[t,s] - rowmax[t])  (128 MB)
__device__ float g_mx[T_MAX];              // rowmax[t]
__device__ float g_loglamT[MDIM * SDIM];   // log(lam_c) transposed: [m][s]
__device__ float g_lamsum[SDIM];
__device__ float g_pi[SDIM];               // exp(combined logpi)

// ---- f32x2 packed-FMA helpers (sm_103a) ----
__device__ __forceinline__ unsigned long long pk2(float lo, float hi) {
    unsigned long long r;
    asm("mov.b64 %0, {%1, %2};" : "=l"(r) : "f"(lo), "f"(hi));
    return r;
}
__device__ __forceinline__ unsigned long long fma2(unsigned long long a,
                                                   unsigned long long b,
                                                   unsigned long long c) {
    unsigned long long d;
    asm("fma.rn.f32x2 %0, %1, %2, %3;" : "=l"(d) : "l"(a), "l"(b), "l"(c));
    return d;
}
__device__ __forceinline__ unsigned long long mul2(unsigned long long a,
                                                   unsigned long long b) {
    unsigned long long d;
    asm("mul.rn.f32x2 %0, %1, %2;" : "=l"(d) : "l"(a), "l"(b));
    return d;
}
__device__ __forceinline__ float hadd2(unsigned long long v) {
    float lo, hi;
    asm("mov.b64 {%0, %1}, %2;" : "=f"(lo), "=f"(hi) : "l"(v));
    return lo + hi;
}

// ============================================================
// Kernel 1: combined rates, log-rates (transposed), priors
// ============================================================
__global__ void setup_kernel(const float* __restrict__ lam1,
                             const float* __restrict__ lam2,
                             const float* __restrict__ lam3,
                             const float* __restrict__ logpi1,
                             const float* __restrict__ logpi2,
                             const float* __restrict__ logpi3) {
    int s = blockIdx.x * blockDim.x + threadIdx.x;
    if (s >= SDIM) return;
    int s1 = s >> 7, s2 = (s >> 3) & 15, s3 = s & 7;
    float lsum = 0.f;
#pragma unroll
    for (int m = 0; m < MDIM; m++) {
        float lam = lam1[s1 * MDIM + m] + lam2[s2 * MDIM + m] + lam3[s3 * MDIM + m];
        lsum += lam;
        g_loglamT[m * SDIM + s] = logf(lam);
    }
    g_lamsum[s] = lsum;
    g_pi[s] = expf(logpi1[s1] + logpi2[s2] + logpi3[s3]);
}

// ============================================================
// Kernel 2: per-timestep emissions, normalized to exp(em - max)
// ============================================================
__global__ void emis_kernel(const int* __restrict__ x) {
    int t = blockIdx.x;
    int tid = threadIdx.x;
    __shared__ float xf[MDIM];
    __shared__ float red[8];

    if (tid < MDIM) xf[tid] = (float)x[t * MDIM + tid];
    __syncthreads();

    float lg = 0.f;
#pragma unroll
    for (int m = 0; m < MDIM; m++) lg += lgammaf(xf[m] + 1.0f);

    float e[8];
#pragma unroll
    for (int j = 0; j < 8; j++) e[j] = 0.f;

#pragma unroll
    for (int m = 0; m < MDIM; m++) {
        float xm = xf[m];
        const float* row = &g_loglamT[m * SDIM];
#pragma unroll
        for (int j = 0; j < 8; j++) e[j] = fmaf(xm, row[tid + j * 256], e[j]);
    }
#pragma unroll
    for (int j = 0; j < 8; j++) e[j] = e[j] - g_lamsum[tid + j * 256] - lg;

    float mloc = -3.4e38f;
#pragma unroll
    for (int j = 0; j < 8; j++) mloc = fmaxf(mloc, e[j]);
#pragma unroll
    for (int o = 16; o > 0; o >>= 1)
        mloc = fmaxf(mloc, __shfl_xor_sync(0xffffffffu, mloc, o));
    if ((tid & 31) == 0) red[tid >> 5] = mloc;
    __syncthreads();
    float mx = red[0];
#pragma unroll
    for (int k = 1; k < 8; k++) mx = fmaxf(mx, red[k]);

    float* outrow = &g_em[(size_t)t * SDIM];
#pragma unroll
    for (int j = 0; j < 8; j++) outrow[tid + j * 256] = expf(e[j] - mx);
    if (tid == 0) g_mx[t] = mx;
}

// ============================================================
// Kernel 3: persistent single-CTA scaled-linear forward scan.
// 512 threads (reg cap 128 -> no spills), 4 outputs/thread.
//
// Layouts (floats):
//   aS[buf][d1*132 + d2*8 + d3]                (d1-pad 132)
//   bS[(p1*8 + d3)*20 + p2]                    (row pad 20)
//   cS[(d2*8 + d3)*20 + (p1 ^ 4*(d2&3))]       (row pad 20, chunk-XOR swizzle)
//   A1p/A2p[row*20 + col]                      (row pad 20)
// All vector loads 16B-aligned (pads are multiples of 4 floats).
// ============================================================
__global__ void __launch_bounds__(512, 1)
scan_kernel(const float* __restrict__ logA1,
            const float* __restrict__ logA2,
            const float* __restrict__ logA3,
            float* __restrict__ out) {
    __shared__ __align__(16) float A1p[16 * 20];
    __shared__ __align__(16) float A2p[16 * 20];
    __shared__ __align__(16) float aS[2][16 * 132];
    __shared__ __align__(16) float bS[128 * 20];
    __shared__ __align__(16) float cS[128 * 20];
    __shared__ float wsum[16];
    __shared__ float SfinInv;

    const int tid = threadIdx.x;
    const int warp = tid >> 5, lane = tid & 31;

    // exp'd, padded transition matrices
    if (tid < 256) {
        A1p[(tid >> 4) * 20 + (tid & 15)] = expf(logA1[tid]);
    } else {
        int u = tid - 256;
        A2p[(u >> 4) * 20 + (u & 15)] = expf(logA2[u]);
    }

    // ---- phase-2 ids: q=(p1,p2) pair, sub in {0,1}; outputs d3 = 4*sub+k
    const int q = tid >> 1;
    const int p2p1 = q >> 4, p2p2 = q & 15, p2sub = tid & 1;
    unsigned long long A3r[4][4];   // A3 rows 4*sub+k, packed by p3 pairs
#pragma unroll
    for (int k = 0; k < 4; k++)
#pragma unroll
        for (int j = 0; j < 4; j++)
            A3r[k][j] = pk2(expf(logA3[(4 * p2sub + k) * 8 + 2 * j]),
                            expf(logA3[(4 * p2sub + k) * 8 + 2 * j + 1]));

    // ---- phase-3 ids: grp=(p1,d3), sub in 0..3; outputs d2 = sub+4k
    const int g3 = tid >> 2;
    const int p3p1 = g3 >> 3, p3d3 = g3 & 7, p3sub = tid & 3;

    // ---- phase-4 ids: grp=(d2,d3), sub in 0..3; outputs d1 = sub+4k
    const int g4 = tid >> 2;
    const int p4d2 = g4 >> 3, p4d3 = g4 & 7, p4sub = tid & 3;
    const int emb = p4d2 * 8 + p4d3;
    const int em_b = p4sub * 128 + emb;        // + k*512
    const int aw_b = p4sub * 132 + emb;        // + k*528
    const int cvbase = (p4d2 * 8 + p4d3) * 20;
    const int sxor = p4d2 & 3;

    double Lacc = 0.0;
    float mx_reg = g_mx[0];

    __syncthreads();

    // ---- t = 0: u = em0 * pi
    {
        float ps = 0.f;
#pragma unroll
        for (int k = 0; k < 4; k++) {
            int ei = em_b + k * 512;
            float u = g_em[ei] * g_pi[ei];
            aS[0][aw_b + k * 528] = u;
            ps += u;
        }
#pragma unroll
        for (int o = 16; o > 0; o >>= 1) ps += __shfl_xor_sync(0xffffffffu, ps, o);
        if (lane == 0) wsum[warp] = ps;
    }
    __syncthreads();

    for (int t = 1; t < T_MAX; t++) {
        const float* acur = &aS[(t - 1) & 1][0];
        float* anext = &aS[t & 1][0];

        // warp0: finalize S_{t-1}; thread0 accumulates log-scale
        if (warp == 0) {
            float s = (lane < 16) ? wsum[lane] : 0.f;
#pragma unroll
            for (int o = 8; o > 0; o >>= 1) s += __shfl_xor_sync(0xffffffffu, s, o);
            if (lane == 0) {
                SfinInv = 1.0f / s;
                Lacc += (double)(mx_reg + logf(s));
            }
        }
        if (tid == 0) mx_reg = g_mx[t];

        // prefetch emissions (consumed in phase 4, ~2 barriers later)
        const float* emt = g_em + (size_t)t * SDIM + em_b;
        float eg0 = emt[0], eg1 = emt[512], eg2 = emt[1024], eg3 = emt[1536];

        // ---- phase 2: b[p1,d3,p2] = sum_p3 A3[d3,p3] * a[p1,p2,p3]
        {
            const float* ap = acur + p2p1 * 132 + p2p2 * 8;
            ulonglong2 V0 = *(const ulonglong2*)ap;
            ulonglong2 V1 = *(const ulonglong2*)(ap + 4);
#pragma unroll
            for (int k = 0; k < 4; k++) {
                unsigned long long acc = mul2(A3r[k][0], V0.x);
                acc = fma2(A3r[k][1], V0.y, acc);
                acc = fma2(A3r[k][2], V1.x, acc);
                acc = fma2(A3r[k][3], V1.y, acc);
                bS[(p2p1 * 8 + 4 * p2sub + k) * 20 + p2p2] = hadd2(acc);
            }
        }
        __syncthreads();

        // ---- phase 3: c[p1,d2,d3] = sum_p2 A2[d2,p2] * b[p1,d3,p2]
        {
            const ulonglong2* bp = (const ulonglong2*)(bS + (p3p1 * 8 + p3d3) * 20);
            ulonglong2 B0 = bp[0], B1 = bp[1], B2 = bp[2], B3 = bp[3];
#pragma unroll
            for (int k = 0; k < 4; k++) {
                int d2 = p3sub + 4 * k;
                const ulonglong2* w = (const ulonglong2*)(A2p + d2 * 20);
                ulonglong2 Wa = w[0], Wb = w[1], Wc = w[2], Wd = w[3];
                unsigned long long acc = mul2(Wa.x, B0.x);
                acc = fma2(Wa.y, B0.y, acc);
                acc = fma2(Wb.x, B1.x, acc);
                acc = fma2(Wb.y, B1.y, acc);
                acc = fma2(Wc.x, B2.x, acc);
                acc = fma2(Wc.y, B2.y, acc);
                acc = fma2(Wd.x, B3.x, acc);
                acc = fma2(Wd.y, B3.y, acc);
                // chunk-XOR swizzle on p1 (d2&3 == p3sub)
                cS[(d2 * 8 + p3d3) * 20 + (p3p1 ^ (4 * p3sub))] = hadd2(acc);
            }
        }
        __syncthreads();

        // ---- phase 4: u[d1,d2,d3] = em*invS * sum_p1 A1[d1,p1]*c[p1,d2,d3]
        {
            const float* crow = cS + cvbase;
            // physical chunk (blk ^ sxor) holds logical p1-block blk
            ulonglong2 CV0 = *(const ulonglong2*)(crow + 4 * (0 ^ sxor));
            ulonglong2 CV1 = *(const ulonglong2*)(crow + 4 * (1 ^ sxor));
            ulonglong2 CV2 = *(const ulonglong2*)(crow + 4 * (2 ^ sxor));
            ulonglong2 CV3 = *(const ulonglong2*)(crow + 4 * (3 ^ sxor));
            float invS = SfinInv;
            float ps = 0.f;
#pragma unroll
            for (int k = 0; k < 4; k++) {
                const ulonglong2* w = (const ulonglong2*)(A1p + (p4sub + 4 * k) * 20);
                ulonglong2 Wa = w[0], Wb = w[1], Wc = w[2], Wd = w[3];
                unsigned long long acc = mul2(Wa.x, CV0.x);
                acc = fma2(Wa.y, CV0.y, acc);
                acc = fma2(Wb.x, CV1.x, acc);
                acc = fma2(Wb.y, CV1.y, acc);
                acc = fma2(Wc.x, CV2.x, acc);
                acc = fma2(Wc.y, CV2.y, acc);
                acc = fma2(Wd.x, CV3.x, acc);
                acc = fma2(Wd.y, CV3.y, acc);
                float eg = (k == 0) ? eg0 : (k == 1) ? eg1 : (k == 2) ? eg2 : eg3;
                float u = eg * invS * hadd2(acc);
                anext[aw_b + k * 528] = u;
                ps += u;
            }
#pragma unroll
            for (int o = 16; o > 0; o >>= 1) ps += __shfl_xor_sync(0xffffffffu, ps, o);
            if (lane == 0) wsum[warp] = ps;
        }
        __syncthreads();
    }

    // final S_{T-1}
    if (warp == 0) {
        float s = (lane < 16) ? wsum[lane] : 0.f;
#pragma unroll
        for (int o = 8; o > 0; o >>= 1) s += __shfl_xor_sync(0xffffffffu, s, o);
        if (lane == 0) {
            Lacc += (double)(mx_reg + logf(s));
            out[0] = (float)Lacc;
        }
    }
}

// ============================================================
extern "C" void kernel_launch(void* const* d_in, const int* in_sizes, int n_in,
                              void* d_out, int out_size) {
    const int*   x      = (const int*)d_in[0];
    const float* lam1   = (const float*)d_in[1];
    const float* lam2   = (const float*)d_in[2];
    const float* lam3   = (const float*)d_in[3];
    const float* logA1  = (const float*)d_in[4];
    const float* logA2  = (const float*)d_in[5];
    const float* logA3  = (const float*)d_in[6];
    const float* logpi1 = (const float*)d_in[7];
    const float* logpi2 = (const float*)d_in[8];
    const float* logpi3 = (const float*)d_in[9];
    float* out = (float*)d_out;

    setup_kernel<<<8, 256>>>(lam1, lam2, lam3, logpi1, logpi2, logpi3);
    emis_kernel<<<T_MAX, 256>>>(x);
    scan_kernel<<<1, 512>>>(logA1, logA2, logA3, out);
}